// round 5
// baseline (speedup 1.0000x reference)
#include <cuda_runtime.h>
#include <math.h>

// Problem constants
#define N_TOKENS 131072
#define E_DIM    128
#define KCODES   1024
#define NUM_Q    4

#define TOK_PER_BLK 128
#define K_TILE      64

// Device-global scratch (no allocations allowed)
__device__ double g_loss;
__device__ float  g_cbnorm[NUM_Q * KCODES];

__global__ void zero_loss_kernel() {
    g_loss = 0.0;
}

// XLA-GPU row-reduction order for sum of squares over a 128-row:
// lane l partial over strided elems {l, l+32, l+64, l+96}, UNFUSED
// (rounded square then plain add), then shfl.down butterfly offsets
// 16,8,4,2,1 (a_l += a_{l+off}), result at lane 0. Simulated in-thread.
__device__ __forceinline__ float rowsumsq_xla_gpu(const float* v /*128 elems*/) {
    float part[32];
#pragma unroll
    for (int l = 0; l < 32; l++) {
        float a = __fmul_rn(v[l], v[l]);                       // fadd(0, x) == x
        a = __fadd_rn(a, __fmul_rn(v[l + 32], v[l + 32]));
        a = __fadd_rn(a, __fmul_rn(v[l + 64], v[l + 64]));
        a = __fadd_rn(a, __fmul_rn(v[l + 96], v[l + 96]));
        part[l] = a;
    }
#pragma unroll
    for (int off = 16; off > 0; off >>= 1) {
#pragma unroll
        for (int l = 0; l < 16; l++) {
            if (l < off) part[l] = __fadd_rn(part[l], part[l + off]);
        }
    }
    return part[0];
}

// C = ||cb_k||^2 with the same XLA-GPU tree order
__global__ void cbnorm_kernel(const float* __restrict__ cbs) {
    int i = blockIdx.x * blockDim.x + threadIdx.x;
    if (i >= NUM_Q * KCODES) return;
    const float* row = cbs + (size_t)i * E_DIM;
    float v[E_DIM];
#pragma unroll 8
    for (int e = 0; e < E_DIM; e++) v[e] = row[e];
    g_cbnorm[i] = rowsumsq_xla_gpu(v);
}

// Main RVQ kernel: one thread per token, residual in registers.
// B dot: fused sequential ascending-k (cuBLAS SGEMM / Eigen gebp order).
// A: XLA-GPU warp-tree order (see rowsumsq_xla_gpu).
// Output layout in d_out (float32):
//   [0, N*E)            x_q
//   [N*E]               mean loss scalar
//   [N*E+1, ...)        indices as float, token-major [N,4]
__global__ void __launch_bounds__(TOK_PER_BLK)
rvq_kernel(const float* __restrict__ x, const float* __restrict__ cbs,
           float* __restrict__ out)
{
    __shared__ float4 sCb[K_TILE][E_DIM / 4];   // 32 KB codebook tile
    __shared__ float  sNorm[K_TILE];

    const int tid = threadIdx.x;
    const int tok = blockIdx.x * TOK_PER_BLK + tid;

    // Residual in registers (starts as x)
    float4 R[E_DIM / 4];
    {
        const float4* xrow = reinterpret_cast<const float4*>(x + (size_t)tok * E_DIM);
#pragma unroll
        for (int i = 0; i < E_DIM / 4; i++) R[i] = __ldg(&xrow[i]);
    }

    float*  xq_base  = out;                                   // [N, E]
    float*  idx_base = out + (size_t)N_TOKENS * E_DIM + 1;    // [N, 4]
    float4* xqrow    = reinterpret_cast<float4*>(xq_base + (size_t)tok * E_DIM);

    float lossAcc = 0.0f;

    for (int q = 0; q < NUM_Q; q++) {
        const float* cb = cbs + (size_t)q * KCODES * E_DIM;

        // A = sum(r*r) in XLA-GPU tree order
        float A;
        {
            const float* rv = reinterpret_cast<const float*>(R);
            A = rowsumsq_xla_gpu(rv);
        }

        float best  = __int_as_float(0x7f800000);  // +inf
        int   bestk = 0;

        for (int k0 = 0; k0 < KCODES; k0 += K_TILE) {
            __syncthreads();   // protect previous tile consumers
            // Cooperative coalesced tile load: K_TILE rows of 128 floats
            {
                const float4* src = reinterpret_cast<const float4*>(cb + (size_t)k0 * E_DIM);
                float4* dst = &sCb[0][0];
#pragma unroll
                for (int i = 0; i < (K_TILE * E_DIM / 4) / TOK_PER_BLK; i++) {
                    int li = tid + i * TOK_PER_BLK;
                    dst[li] = src[li];
                }
                if (tid < K_TILE) sNorm[tid] = g_cbnorm[q * KCODES + k0 + tid];
            }
            __syncthreads();

            // 8 codes per register pass; dot = sequential fused FMA, e ascending
            // (cuBLAS SGEMM / Eigen gebp accumulation order)
#pragma unroll 1
            for (int kg = 0; kg < K_TILE; kg += 8) {
                float acc[8];
#pragma unroll
                for (int c = 0; c < 8; c++) acc[c] = 0.0f;

#pragma unroll
                for (int e = 0; e < E_DIM / 4; e++) {
                    float4 rv = R[e];
#pragma unroll
                    for (int c = 0; c < 8; c++) {
                        float4 cv = sCb[kg + c][e];   // broadcast LDS
                        float a = acc[c];
                        a = fmaf(rv.x, cv.x, a);
                        a = fmaf(rv.y, cv.y, a);
                        a = fmaf(rv.z, cv.z, a);
                        a = fmaf(rv.w, cv.w, a);
                        acc[c] = a;
                    }
                }
#pragma unroll
                for (int c = 0; c < 8; c++) {
                    // d = fl(fl(A - fl(2*B)) + C) — reference expression tree
                    float s = __fadd_rn(__fsub_rn(A, __fmul_rn(2.0f, acc[c])),
                                        sNorm[kg + c]);
                    if (s < best) { best = s; bestk = k0 + kg + c; }  // first-min
                }
            }
        }

        // Gather chosen code, straight-through rounding, residual + x_q update
        const float4* qrow = reinterpret_cast<const float4*>(cb + (size_t)bestk * E_DIM);
#pragma unroll
        for (int i = 0; i < E_DIM / 4; i++) {
            float4 qv = __ldg(&qrow[i]);
            float4 rv = R[i];
            float4 qz, rn, xv;
            // quantized = fl(r + fl(q - r))
            qz.x = __fadd_rn(rv.x, __fsub_rn(qv.x, rv.x));
            qz.y = __fadd_rn(rv.y, __fsub_rn(qv.y, rv.y));
            qz.z = __fadd_rn(rv.z, __fsub_rn(qv.z, rv.z));
            qz.w = __fadd_rn(rv.w, __fsub_rn(qv.w, rv.w));
            // next residual = fl(r - quantized)
            rn.x = __fsub_rn(rv.x, qz.x);
            rn.y = __fsub_rn(rv.y, qz.y);
            rn.z = __fsub_rn(rv.z, qz.z);
            rn.w = __fsub_rn(rv.w, qz.w);
            // loss: rounded square, accumulated (order-insensitive at tol)
            lossAcc = __fadd_rn(lossAcc, __fmul_rn(rn.x, rn.x));
            lossAcc = __fadd_rn(lossAcc, __fmul_rn(rn.y, rn.y));
            lossAcc = __fadd_rn(lossAcc, __fmul_rn(rn.z, rn.z));
            lossAcc = __fadd_rn(lossAcc, __fmul_rn(rn.w, rn.w));
            // x_q accumulated in d_out (left fold over stages)
            if (q == 0) {
                xv = qz;
            } else {
                xv = xqrow[i];
                xv.x = __fadd_rn(xv.x, qz.x);
                xv.y = __fadd_rn(xv.y, qz.y);
                xv.z = __fadd_rn(xv.z, qz.z);
                xv.w = __fadd_rn(xv.w, qz.w);
            }
            xqrow[i] = xv;
            R[i] = rn;
        }
        idx_base[(size_t)tok * NUM_Q + q] = (float)bestk;
    }

    // Loss reduction: warp shuffle, then one double atomic per warp
#pragma unroll
    for (int o = 16; o > 0; o >>= 1)
        lossAcc += __shfl_xor_sync(0xffffffffu, lossAcc, o);
    if ((tid & 31) == 0) atomicAdd(&g_loss, (double)lossAcc);
}

__global__ void finalize_loss_kernel(float* __restrict__ out) {
    double v = g_loss * (0.25 / ((double)NUM_Q * (double)N_TOKENS * (double)E_DIM));
    out[(size_t)N_TOKENS * E_DIM] = (float)v;
}

extern "C" void kernel_launch(void* const* d_in, const int* in_sizes, int n_in,
                              void* d_out, int out_size)
{
    const float* x   = (const float*)d_in[0];   // [131072, 128]
    const float* cbs = (const float*)d_in[1];   // [4, 1024, 128]
    float* out = (float*)d_out;

    zero_loss_kernel<<<1, 1>>>();
    cbnorm_kernel<<<(NUM_Q * KCODES + 127) / 128, 128>>>(cbs);
    rvq_kernel<<<N_TOKENS / TOK_PER_BLK, TOK_PER_BLK>>>(x, cbs, out);
    finalize_loss_kernel<<<1, 1>>>(out);
}

// round 6
// speedup vs baseline: 1.0024x; 1.0024x over previous
#include <cuda_runtime.h>
#include <math.h>

// Problem constants
#define N_TOKENS 131072
#define E_DIM    128
#define KCODES   1024
#define NUM_Q    4

#define TOK_PER_BLK 128
#define K_TILE      64

// Device-global scratch (no allocations allowed)
__device__ double g_loss;
__device__ float  g_cbnorm[NUM_Q * KCODES];

__global__ void zero_loss_kernel() {
    g_loss = 0.0;
}

// XLA-GPU row-reduction order for sum of squares over a 128-row:
// lane l partial over strided elems {l, l+32, l+64, l+96}, UNFUSED
// (rounded square then plain add), then shfl.down butterfly offsets
// 16,8,4,2,1 (a_l += a_{l+off}), result at lane 0. Simulated in-thread.
__device__ __forceinline__ float rowsumsq_xla_gpu(const float* v /*128 elems*/) {
    float part[32];
#pragma unroll
    for (int l = 0; l < 32; l++) {
        float a = __fmul_rn(v[l], v[l]);                       // fadd(0, x) == x
        a = __fadd_rn(a, __fmul_rn(v[l + 32], v[l + 32]));
        a = __fadd_rn(a, __fmul_rn(v[l + 64], v[l + 64]));
        a = __fadd_rn(a, __fmul_rn(v[l + 96], v[l + 96]));
        part[l] = a;
    }
#pragma unroll
    for (int off = 16; off > 0; off >>= 1) {
#pragma unroll
        for (int l = 0; l < 16; l++) {
            if (l < off) part[l] = __fadd_rn(part[l], part[l + off]);
        }
    }
    return part[0];
}

// C = ||cb_k||^2 with the same XLA-GPU tree order
__global__ void cbnorm_kernel(const float* __restrict__ cbs) {
    int i = blockIdx.x * blockDim.x + threadIdx.x;
    if (i >= NUM_Q * KCODES) return;
    const float* row = cbs + (size_t)i * E_DIM;
    float v[E_DIM];
#pragma unroll 8
    for (int e = 0; e < E_DIM; e++) v[e] = row[e];
    g_cbnorm[i] = rowsumsq_xla_gpu(v);
}

// Main RVQ kernel: one thread per token, residual in registers.
// B dot: fused sequential ascending-k (cuBLAS SGEMM / Eigen gebp order).
// A: XLA-GPU warp-tree order (see rowsumsq_xla_gpu).
// Output layout in d_out (float32):
//   [0, N*E)            x_q
//   [N*E]               mean loss scalar
//   [N*E+1, ...)        indices as float, token-major [N,4]
__global__ void __launch_bounds__(TOK_PER_BLK)
rvq_kernel(const float* __restrict__ x, const float* __restrict__ cbs,
           float* __restrict__ out)
{
    __shared__ float4 sCb[K_TILE][E_DIM / 4];   // 32 KB codebook tile
    __shared__ float  sNorm[K_TILE];

    const int tid = threadIdx.x;
    const int tok = blockIdx.x * TOK_PER_BLK + tid;

    // Residual in registers (starts as x)
    float4 R[E_DIM / 4];
    {
        const float4* xrow = reinterpret_cast<const float4*>(x + (size_t)tok * E_DIM);
#pragma unroll
        for (int i = 0; i < E_DIM / 4; i++) R[i] = __ldg(&xrow[i]);
    }

    float*  xq_base  = out;                                   // [N, E]
    float*  idx_base = out + (size_t)N_TOKENS * E_DIM + 1;    // [N, 4]
    float4* xqrow    = reinterpret_cast<float4*>(xq_base + (size_t)tok * E_DIM);

    float lossAcc = 0.0f;

    for (int q = 0; q < NUM_Q; q++) {
        const float* cb = cbs + (size_t)q * KCODES * E_DIM;

        // A = sum(r*r) in XLA-GPU tree order
        float A;
        {
            const float* rv = reinterpret_cast<const float*>(R);
            A = rowsumsq_xla_gpu(rv);
        }

        float best  = __int_as_float(0x7f800000);  // +inf
        int   bestk = 0;

        for (int k0 = 0; k0 < KCODES; k0 += K_TILE) {
            __syncthreads();   // protect previous tile consumers
            // Cooperative coalesced tile load: K_TILE rows of 128 floats
            {
                const float4* src = reinterpret_cast<const float4*>(cb + (size_t)k0 * E_DIM);
                float4* dst = &sCb[0][0];
#pragma unroll
                for (int i = 0; i < (K_TILE * E_DIM / 4) / TOK_PER_BLK; i++) {
                    int li = tid + i * TOK_PER_BLK;
                    dst[li] = src[li];
                }
                if (tid < K_TILE) sNorm[tid] = g_cbnorm[q * KCODES + k0 + tid];
            }
            __syncthreads();

            // 8 codes per register pass; dot = sequential fused FMA, e ascending
            // (cuBLAS SGEMM / Eigen gebp accumulation order)
#pragma unroll 1
            for (int kg = 0; kg < K_TILE; kg += 8) {
                float acc[8];
#pragma unroll
                for (int c = 0; c < 8; c++) acc[c] = 0.0f;

#pragma unroll
                for (int e = 0; e < E_DIM / 4; e++) {
                    float4 rv = R[e];
#pragma unroll
                    for (int c = 0; c < 8; c++) {
                        float4 cv = sCb[kg + c][e];   // broadcast LDS
                        float a = acc[c];
                        a = fmaf(rv.x, cv.x, a);
                        a = fmaf(rv.y, cv.y, a);
                        a = fmaf(rv.z, cv.z, a);
                        a = fmaf(rv.w, cv.w, a);
                        acc[c] = a;
                    }
                }
#pragma unroll
                for (int c = 0; c < 8; c++) {
                    // d = fl(fl(A - fl(2*B)) + C) — reference expression tree
                    float s = __fadd_rn(__fsub_rn(A, __fmul_rn(2.0f, acc[c])),
                                        sNorm[kg + c]);
                    if (s < best) { best = s; bestk = k0 + kg + c; }  // first-min
                }
            }
        }

        // Gather chosen code, straight-through rounding, residual + x_q update
        const float4* qrow = reinterpret_cast<const float4*>(cb + (size_t)bestk * E_DIM);
#pragma unroll
        for (int i = 0; i < E_DIM / 4; i++) {
            float4 qv = __ldg(&qrow[i]);
            float4 rv = R[i];
            float4 qz, rn, xv;
            // quantized = fl(r + fl(q - r))
            qz.x = __fadd_rn(rv.x, __fsub_rn(qv.x, rv.x));
            qz.y = __fadd_rn(rv.y, __fsub_rn(qv.y, rv.y));
            qz.z = __fadd_rn(rv.z, __fsub_rn(qv.z, rv.z));
            qz.w = __fadd_rn(rv.w, __fsub_rn(qv.w, rv.w));
            // next residual = fl(r - quantized)
            rn.x = __fsub_rn(rv.x, qz.x);
            rn.y = __fsub_rn(rv.y, qz.y);
            rn.z = __fsub_rn(rv.z, qz.z);
            rn.w = __fsub_rn(rv.w, qz.w);
            // loss: rounded square, accumulated (order-insensitive at tol)
            lossAcc = __fadd_rn(lossAcc, __fmul_rn(rn.x, rn.x));
            lossAcc = __fadd_rn(lossAcc, __fmul_rn(rn.y, rn.y));
            lossAcc = __fadd_rn(lossAcc, __fmul_rn(rn.z, rn.z));
            lossAcc = __fadd_rn(lossAcc, __fmul_rn(rn.w, rn.w));
            // x_q accumulated in d_out (left fold over stages)
            if (q == 0) {
                xv = qz;
            } else {
                xv = xqrow[i];
                xv.x = __fadd_rn(xv.x, qz.x);
                xv.y = __fadd_rn(xv.y, qz.y);
                xv.z = __fadd_rn(xv.z, qz.z);
                xv.w = __fadd_rn(xv.w, qz.w);
            }
            xqrow[i] = xv;
            R[i] = rn;
        }
        idx_base[(size_t)tok * NUM_Q + q] = (float)bestk;
    }

    // Loss reduction: warp shuffle, then one double atomic per warp
#pragma unroll
    for (int o = 16; o > 0; o >>= 1)
        lossAcc += __shfl_xor_sync(0xffffffffu, lossAcc, o);
    if ((tid & 31) == 0) atomicAdd(&g_loss, (double)lossAcc);
}

__global__ void finalize_loss_kernel(float* __restrict__ out) {
    double v = g_loss * (0.25 / ((double)NUM_Q * (double)N_TOKENS * (double)E_DIM));
    out[(size_t)N_TOKENS * E_DIM] = (float)v;
}

extern "C" void kernel_launch(void* const* d_in, const int* in_sizes, int n_in,
                              void* d_out, int out_size)
{
    const float* x   = (const float*)d_in[0];   // [131072, 128]
    const float* cbs = (const float*)d_in[1];   // [4, 1024, 128]
    float* out = (float*)d_out;

    zero_loss_kernel<<<1, 1>>>();
    cbnorm_kernel<<<(NUM_Q * KCODES + 127) / 128, 128>>>(cbs);
    rvq_kernel<<<N_TOKENS / TOK_PER_BLK, TOK_PER_BLK>>>(x, cbs, out);
    finalize_loss_kernel<<<1, 1>>>(out);
}